// round 8
// baseline (speedup 1.0000x reference)
#include <cuda_runtime.h>
#include <cuda_fp16.h>
#include <cstdint>

#define M_DIM 4096
#define K_DIM 4096
#define N_DIM 11008
#define NPACK (N_DIM / 8)   // 1376
#define GROUP 128

// Static scratch: W [K, N] fp16 (90.2 MB) + X [M, K] fp16 (32 MB).
__device__ __half g_W[(size_t)K_DIM * N_DIM];
__device__ __half g_X[(size_t)M_DIM * K_DIM];

// ---------------------------------------------------------------------------
// Kernel 0+1 fused: block.x < CONV_BLOCKS -> convert x; else AWQ dequant.
// ---------------------------------------------------------------------------
constexpr int CONV_BLOCKS = (M_DIM * K_DIM / 8) / 256;          // 8192
constexpr int DEQ_ELEMS   = K_DIM * NPACK;                      // 5,636,096
constexpr int DEQ_BLOCKS  = (DEQ_ELEMS + 255) / 256;            // 22016

__global__ void __launch_bounds__(256) prep_kernel(
    const float* __restrict__ x,
    const int* __restrict__ qweight,
    const int* __restrict__ qzeros,
    const float* __restrict__ scales)
{
    if (blockIdx.x < CONV_BLOCKS) {
        size_t i = ((size_t)blockIdx.x * 256 + threadIdx.x) * 8;
        float4 v0 = *reinterpret_cast<const float4*>(x + i);
        float4 v1 = *reinterpret_cast<const float4*>(x + i + 4);
        __half2 o[4];
        o[0] = __floats2half2_rn(v0.x, v0.y);
        o[1] = __floats2half2_rn(v0.z, v0.w);
        o[2] = __floats2half2_rn(v1.x, v1.y);
        o[3] = __floats2half2_rn(v1.z, v1.w);
        *reinterpret_cast<uint4*>(&g_X[i]) = *reinterpret_cast<const uint4*>(o);
        return;
    }
    int idx = (blockIdx.x - CONV_BLOCKS) * 256 + threadIdx.x;
    if (idx >= DEQ_ELEMS) return;
    int k = idx / NPACK;
    int c = idx - k * NPACK;
    int g = k >> 7;

    unsigned q = (unsigned)qweight[idx];
    unsigned z = (unsigned)qzeros[g * NPACK + c];

    float4 s0 = *reinterpret_cast<const float4*>(scales + (size_t)g * N_DIM + (size_t)c * 8);
    float4 s1 = *reinterpret_cast<const float4*>(scales + (size_t)g * N_DIM + (size_t)c * 8 + 4);
    float sf[8] = {s0.x, s0.y, s0.z, s0.w, s1.x, s1.y, s1.z, s1.w};

    const int shifts[8] = {0, 16, 4, 20, 8, 24, 12, 28};
    __half2 out[4];
#pragma unroll
    for (int j = 0; j < 4; ++j) {
        int i0 = (int)((q >> shifts[2 * j]) & 0xF) - (int)((z >> shifts[2 * j]) & 0xF);
        int i1 = (int)((q >> shifts[2 * j + 1]) & 0xF) - (int)((z >> shifts[2 * j + 1]) & 0xF);
        out[j] = __floats2half2_rn((float)i0 * sf[2 * j], (float)i1 * sf[2 * j + 1]);
    }
    *reinterpret_cast<uint4*>(&g_W[(size_t)k * N_DIM + (size_t)c * 8]) =
        *reinterpret_cast<const uint4*>(out);
}

// ---------------------------------------------------------------------------
// Kernel 2: persistent pipelined HMMA GEMM.
// CTA tile 128x128, BK=64, 3-stage cp.async, 4 warps (2x2), warp tile 64x64.
// 296 persistent CTAs (2/SM); pipeline runs continuously across tiles.
// ---------------------------------------------------------------------------
constexpr int BM = 128, BN = 128, BK = 64;
constexpr int NK = K_DIM / BK;          // 64 (power of 2)
constexpr int A_LD = BK + 8;            // 72 halves
constexpr int B_LD = BN + 8;            // 136 halves
constexpr int A_STAGE = BM * A_LD;      // 9216 halves
constexpr int B_STAGE = BK * B_LD;      // 8704 halves
constexpr int STAGE_H = A_STAGE + B_STAGE;       // 17920 halves
constexpr int NSTAGE = 3;
constexpr int GEMM_SMEM = NSTAGE * STAGE_H * 2;  // 107,520 B
constexpr int NTHREADS = 128;
constexpr int GROUP_M = 16;
constexpr int MT = M_DIM / BM;          // 32
constexpr int NT = N_DIM / BN;          // 86
constexpr int TOTAL_TILES = MT * NT;    // 2752
constexpr int NCTA = 296;               // 148 SMs x 2

extern __shared__ __half smem_h[];

__device__ __forceinline__ uint32_t smem_u32(const void* p) {
    uint32_t a;
    asm("{ .reg .u64 t; cvta.to.shared.u64 t, %1; cvt.u32.u64 %0, t; }"
        : "=r"(a) : "l"(p));
    return a;
}
__device__ __forceinline__ void cpa16(uint32_t s, const void* g) {
    asm volatile("cp.async.cg.shared.global [%0], [%1], 16;\n" :: "r"(s), "l"(g));
}
#define CP_COMMIT() asm volatile("cp.async.commit_group;\n" ::: "memory")
#define CP_WAIT(n)  asm volatile("cp.async.wait_group %0;\n" :: "n"(n) : "memory")

__device__ __forceinline__ void ldsm_x4(uint32_t& r0, uint32_t& r1, uint32_t& r2,
                                        uint32_t& r3, uint32_t addr) {
    asm volatile("ldmatrix.sync.aligned.m8n8.x4.shared.b16 {%0,%1,%2,%3}, [%4];"
                 : "=r"(r0), "=r"(r1), "=r"(r2), "=r"(r3) : "r"(addr));
}
__device__ __forceinline__ void ldsm_x4_t(uint32_t& r0, uint32_t& r1, uint32_t& r2,
                                          uint32_t& r3, uint32_t addr) {
    asm volatile("ldmatrix.sync.aligned.m8n8.x4.trans.shared.b16 {%0,%1,%2,%3}, [%4];"
                 : "=r"(r0), "=r"(r1), "=r"(r2), "=r"(r3) : "r"(addr));
}
__device__ __forceinline__ void mma16816(float* c, const uint32_t* a, const uint32_t* b) {
    asm volatile(
        "mma.sync.aligned.m16n8k16.row.col.f32.f16.f16.f32 "
        "{%0,%1,%2,%3}, {%4,%5,%6,%7}, {%8,%9}, {%0,%1,%2,%3};"
        : "+f"(c[0]), "+f"(c[1]), "+f"(c[2]), "+f"(c[3])
        : "r"(a[0]), "r"(a[1]), "r"(a[2]), "r"(a[3]), "r"(b[0]), "r"(b[1]));
}

__device__ __forceinline__ void tile_coords(int t, int& m0, int& n0) {
    int grp = t / (GROUP_M * NT);
    int rem = t - grp * (GROUP_M * NT);
    int mt  = grp * GROUP_M + rem % GROUP_M;
    int nt  = rem / GROUP_M;
    m0 = mt * BM;
    n0 = nt * BN;
}

// stage load (128 threads): A 1024 chunks + B 1024 chunks, 8 iters each.
__device__ __forceinline__ void load_stage(uint32_t sb, int tid, int m0, int n0, int kt)
{
    uint32_t a_s = sb;
    uint32_t b_s = sb + A_STAGE * 2;
#pragma unroll
    for (int i = 0; i < 8; ++i) {
        int cid = tid + NTHREADS * i;
        int row = cid >> 3;
        int kc  = cid & 7;
        cpa16(a_s + (row * A_LD + kc * 8) * 2,
              g_X + (size_t)(m0 + row) * K_DIM + kt + kc * 8);
    }
#pragma unroll
    for (int i = 0; i < 8; ++i) {
        int cid = tid + NTHREADS * i;
        int row = cid >> 4;
        int nc  = cid & 15;
        cpa16(b_s + (row * B_LD + nc * 8) * 2,
              g_W + (size_t)(kt + row) * N_DIM + n0 + nc * 8);
    }
}

__global__ void __launch_bounds__(NTHREADS, 2) gemm_kernel(
    const float* __restrict__ bias,
    float* __restrict__ out)
{
    const int tid  = threadIdx.x;
    const int warp = tid >> 5;
    const int lane = tid & 31;
    const int wm = warp >> 1;           // 0..1
    const int wn = warp & 1;            // 0..1

    const int cta = blockIdx.x;         // 0..295
    const int ntiles = (TOTAL_TILES - cta + NCTA - 1) / NCTA;   // 9 or 10
    if (ntiles <= 0) return;
    const int total_j = ntiles * NK;

    const uint32_t sb = smem_u32(smem_h);

    float c[4][8][4];
#pragma unroll
    for (int i = 0; i < 4; ++i)
#pragma unroll
        for (int j = 0; j < 8; ++j)
#pragma unroll
            for (int e = 0; e < 4; ++e) c[i][j][e] = 0.0f;

    // compute-side and prefetch-side tile coords
    int cm0, cn0, pm0, pn0;
    tile_coords(cta, cm0, cn0);
    pm0 = cm0; pn0 = cn0;

    // Prologue: iters 0, 1 of first tile
    load_stage(sb, tid, pm0, pn0, 0);
    CP_COMMIT();
    load_stage(sb + STAGE_H * 2, tid, pm0, pn0, BK);
    CP_COMMIT();

    const int a_row = lane & 15;
    const int a_c8  = (lane >> 4) * 8;
    const int b_row = lane & 15;
    const int b_c8  = (lane >> 4) * 8;
    const int qr = lane >> 2;
    const int qc = (lane & 3) * 2;

    int slot = 0;       // j % 3
    int pslot = 2;      // (j+2) % 3

    for (int j = 0; j < total_j; ++j) {
        CP_WAIT(1);
        __syncthreads();

        int jp = j + 2;
        if (jp < total_j) {
            int pit = jp & (NK - 1);
            if (pit == 0)
                tile_coords(cta + (jp >> 6) * NCTA, pm0, pn0);
            load_stage(sb + pslot * STAGE_H * 2, tid, pm0, pn0, pit * BK);
        }
        CP_COMMIT();

        const uint32_t a_s = sb + slot * STAGE_H * 2;
        const uint32_t b_s = a_s + A_STAGE * 2;

#pragma unroll
        for (int ks = 0; ks < BK / 16; ++ks) {
            uint32_t af[4][4];
#pragma unroll
            for (int mf = 0; mf < 4; ++mf)
                ldsm_x4(af[mf][0], af[mf][1], af[mf][2], af[mf][3],
                        a_s + ((wm * 64 + mf * 16 + a_row) * A_LD + ks * 16 + a_c8) * 2);
            uint32_t bf[4][4];
#pragma unroll
            for (int nb = 0; nb < 4; ++nb)
                ldsm_x4_t(bf[nb][0], bf[nb][1], bf[nb][2], bf[nb][3],
                          b_s + ((ks * 16 + b_row) * B_LD + wn * 64 + nb * 16 + b_c8) * 2);
#pragma unroll
            for (int mf = 0; mf < 4; ++mf) {
#pragma unroll
                for (int nf = 0; nf < 8; ++nf) {
                    const uint32_t* bp = &bf[nf >> 1][(nf & 1) * 2];
                    mma16816(c[mf][nf], af[mf], bp);
                }
            }
        }

        // slot advance
        slot  = (slot == 2)  ? 0 : slot + 1;
        pslot = (pslot == 2) ? 0 : pslot + 1;

        if ((j & (NK - 1)) == NK - 1) {
            // -------- epilogue for tile j>>6 (registers -> DRAM) --------
#pragma unroll
            for (int nf = 0; nf < 8; ++nf) {
                int col = cn0 + wn * 64 + nf * 8 + qc;
                float2 bv = *reinterpret_cast<const float2*>(bias + col);
                __half bh0 = __float2half(bv.x), bh1 = __float2half(bv.y);
#pragma unroll
                for (int mf = 0; mf < 4; ++mf) {
                    int row = cm0 + wm * 64 + mf * 16 + qr;
                    float2 o0, o1;
                    o0.x = __half2float(__hadd(__float2half(c[mf][nf][0]), bh0));
                    o0.y = __half2float(__hadd(__float2half(c[mf][nf][1]), bh1));
                    o1.x = __half2float(__hadd(__float2half(c[mf][nf][2]), bh0));
                    o1.y = __half2float(__hadd(__float2half(c[mf][nf][3]), bh1));
                    *reinterpret_cast<float2*>(&out[(size_t)row * N_DIM + col]) = o0;
                    *reinterpret_cast<float2*>(&out[(size_t)(row + 8) * N_DIM + col]) = o1;
                }
            }
            // zero accumulators + advance compute tile coords
#pragma unroll
            for (int i = 0; i < 4; ++i)
#pragma unroll
                for (int jj = 0; jj < 8; ++jj)
#pragma unroll
                    for (int e = 0; e < 4; ++e) c[i][jj][e] = 0.0f;
            int nt2 = (j >> 6) + 1;
            if (nt2 < ntiles)
                tile_coords(cta + nt2 * NCTA, cm0, cn0);
        }
    }
}

// ---------------------------------------------------------------------------
extern "C" void kernel_launch(void* const* d_in, const int* in_sizes, int n_in,
                              void* d_out, int out_size)
{
    const float* x      = (const float*)d_in[0];
    const int*   qw     = (const int*)d_in[1];
    const int*   qz     = (const int*)d_in[2];
    const float* scales = (const float*)d_in[3];
    const float* bias   = (const float*)d_in[4];
    float*       out    = (float*)d_out;

    cudaFuncSetAttribute(gemm_kernel, cudaFuncAttributeMaxDynamicSharedMemorySize,
                         GEMM_SMEM);

    prep_kernel<<<CONV_BLOCKS + DEQ_BLOCKS, 256>>>(x, qw, qz, scales);
    gemm_kernel<<<NCTA, NTHREADS, GEMM_SMEM>>>(bias, out);
}